// round 7
// baseline (speedup 1.0000x reference)
#include <cuda_runtime.h>
#include <math.h>
#include <float.h>

#define KDIM 7168
#define NEXP 256
#define NGRP 8
#define GSIZE 32
#define TOPKN 8
#define TOPG 4
#define TTOT 8192
#define BSZ 2
#define SEQ 4096

// Scratch (no cudaMalloc allowed)
__device__ float g_logits[(size_t)TTOT * NEXP];   // 8 MB
__device__ float g_counts[BSZ * NEXP];
__device__ float g_ssum[BSZ * NEXP];

// ---------------------------------------------------------------------------
// XLA-style logistic: sigmoid(x) = 0.5 + 0.5 * tanh_xla(0.5 * x).
// (rational tanh, clamp +-7.90531110763549805, |t|<4e-4 -> t)
// ---------------------------------------------------------------------------
__device__ __forceinline__ float xla_sigmoid(float x) {
    float t  = __fmul_rn(0.5f, x);
    float tc = fminf(fmaxf(t, -7.90531110763549805f), 7.90531110763549805f);
    float x2 = __fmul_rn(tc, tc);
    float p = -2.76076847742355e-16f;
    p = __fadd_rn(__fmul_rn(p, x2),  2.00018790482477e-13f);
    p = __fadd_rn(__fmul_rn(p, x2), -8.60467152213735e-11f);
    p = __fadd_rn(__fmul_rn(p, x2),  5.12229709037114e-08f);
    p = __fadd_rn(__fmul_rn(p, x2),  1.48572235717979e-05f);
    p = __fadd_rn(__fmul_rn(p, x2),  6.37261928875436e-04f);
    p = __fadd_rn(__fmul_rn(p, x2),  4.89352455891786e-03f);
    p = __fmul_rn(p, tc);
    float q = 1.19825839466702e-06f;
    q = __fadd_rn(__fmul_rn(q, x2), 1.18534705686654e-04f);
    q = __fadd_rn(__fmul_rn(q, x2), 2.26843463243900e-03f);
    q = __fadd_rn(__fmul_rn(q, x2), 4.89352518554385e-03f);
    float th = __fdiv_rn(p, q);
    th = (fabsf(t) < 0.0004f) ? t : th;
    return __fadd_rn(0.5f, __fmul_rn(0.5f, th));
}

__global__ void zero_kernel() {
    int i = threadIdx.x;
    if (i < BSZ * NEXP) { g_counts[i] = 0.0f; g_ssum[i] = 0.0f; }
}

// ---------------------------------------------------------------------------
// GEMM: logits[t][e] = sum_k x[t][k] * W[e][k]   (NT, both K-major)
// BM=128, BN=128, BK=8, 256 threads, 8x8 micro-tile per thread.
// Strict ascending-k single-accumulator FMA chain per output (bit-stable).
// ---------------------------------------------------------------------------
__global__ __launch_bounds__(256) void gemm_kernel(const float* __restrict__ A,
                                                   const float* __restrict__ B) {
    __shared__ float As[8][128];
    __shared__ float Bs[8][128];
    const int tid = threadIdx.x;
    const int tx = tid & 15;
    const int ty = tid >> 4;
    const int t0 = blockIdx.y * 128;
    const int e0 = blockIdx.x * 128;
    const float* Ab = A + (size_t)t0 * KDIM;
    const float* Bb = B + (size_t)e0 * KDIM;
    const int lr = tid >> 1;          // 0..127
    const int lc = (tid & 1) * 4;     // 0 or 4

    float acc[8][8];
#pragma unroll
    for (int i = 0; i < 8; i++)
#pragma unroll
        for (int j = 0; j < 8; j++) acc[i][j] = 0.0f;

    float4 av = *(const float4*)(Ab + (size_t)lr * KDIM + lc);
    float4 bv = *(const float4*)(Bb + (size_t)lr * KDIM + lc);

    for (int k0 = 0; k0 < KDIM; k0 += 8) {
        __syncthreads();
        As[lc + 0][lr] = av.x; As[lc + 1][lr] = av.y;
        As[lc + 2][lr] = av.z; As[lc + 3][lr] = av.w;
        Bs[lc + 0][lr] = bv.x; Bs[lc + 1][lr] = bv.y;
        Bs[lc + 2][lr] = bv.z; Bs[lc + 3][lr] = bv.w;
        __syncthreads();
        if (k0 + 8 < KDIM) {
            av = *(const float4*)(Ab + (size_t)lr * KDIM + k0 + 8 + lc);
            bv = *(const float4*)(Bb + (size_t)lr * KDIM + k0 + 8 + lc);
        }
#pragma unroll
        for (int kk = 0; kk < 8; kk++) {
            float4 a0 = *(const float4*)&As[kk][ty * 4];
            float4 a1 = *(const float4*)&As[kk][64 + ty * 4];
            float4 b0 = *(const float4*)&Bs[kk][tx * 4];
            float4 b1 = *(const float4*)&Bs[kk][64 + tx * 4];
            float a[8] = {a0.x, a0.y, a0.z, a0.w, a1.x, a1.y, a1.z, a1.w};
            float b[8] = {b0.x, b0.y, b0.z, b0.w, b1.x, b1.y, b1.z, b1.w};
#pragma unroll
            for (int i = 0; i < 8; i++)
#pragma unroll
                for (int j = 0; j < 8; j++) acc[i][j] = __fmaf_rn(a[i], b[j], acc[i][j]);
        }
    }

#pragma unroll
    for (int hm = 0; hm < 2; hm++) {
#pragma unroll
        for (int i = 0; i < 4; i++) {
            int row = t0 + hm * 64 + ty * 4 + i;
            float* Crow = g_logits + (size_t)row * NEXP + e0;
            int mi = hm * 4 + i;
            *(float4*)&Crow[tx * 4] =
                make_float4(acc[mi][0], acc[mi][1], acc[mi][2], acc[mi][3]);
            *(float4*)&Crow[64 + tx * 4] =
                make_float4(acc[mi][4], acc[mi][5], acc[mi][6], acc[mi][7]);
        }
    }
}

// ---------------------------------------------------------------------------
// Routing: one warp per token. Lane l owns experts {32j+l : j=0..7}
// (global expert index = j*32 + l; lexicographic (j,l) = ascending index).
// Top-8: warp-max score, then MIN INDEX among scores within a ~2-ulp window
// of the max. Exact top-k for separated scores; index-ascending for ulp-scale
// ties — matching jax.lax.top_k behavior on the reference's rounded scores.
// ---------------------------------------------------------------------------
__global__ __launch_bounds__(256) void route_kernel(const float* __restrict__ bias,
                                                    float* __restrict__ out) {
    const unsigned FULL = 0xffffffffu;
    int warp = (blockIdx.x * blockDim.x + threadIdx.x) >> 5;
    int l = threadIdx.x & 31;
    if (warp >= TTOT) return;
    const int t = warp;
    const int b = t / SEQ;
    const float* lgp = g_logits + (size_t)t * NEXP;

    float orig[NGRP], val[NGRP], gscore[NGRP];
#pragma unroll
    for (int j = 0; j < NGRP; j++) {
        float xv = lgp[j * GSIZE + l];
        float s = xla_sigmoid(xv);
        orig[j] = s;
        val[j] = __fadd_rn(s, bias[j * GSIZE + l]);
    }

    // group scores: sum of top-2 (biased) per group
#pragma unroll
    for (int j = 0; j < NGRP; j++) {
        float m1 = val[j], m2 = -FLT_MAX;
#pragma unroll
        for (int off = 16; off > 0; off >>= 1) {
            float o1 = __shfl_xor_sync(FULL, m1, off);
            float o2 = __shfl_xor_sync(FULL, m2, off);
            float hi = fmaxf(m1, o1);
            float lo = fminf(m1, o1);
            m2 = fmaxf(fmaxf(m2, o2), lo);
            m1 = hi;
        }
        gscore[j] = __fadd_rn(m1, m2);
    }

    // top-4 groups (strict > => lowest index on ties)
    unsigned gsel = 0;
    for (int r = 0; r < TOPG; r++) {
        float best = -FLT_MAX; int bi = 0;
#pragma unroll
        for (int j = 0; j < NGRP; j++)
            if (!((gsel >> j) & 1u) && gscore[j] > best) { best = gscore[j]; bi = j; }
        gsel |= 1u << bi;
    }
#pragma unroll
    for (int j = 0; j < NGRP; j++)
        if (!((gsel >> j) & 1u)) val[j] = -FLT_MAX;   // exclude masked groups

    // top-8 experts with ulp-window tie handling
    float wsel[TOPKN]; int isel[TOPKN];
#pragma unroll
    for (int r = 0; r < TOPKN; r++) {
        // warp-wide max score
        float m = -FLT_MAX;
#pragma unroll
        for (int j = 0; j < NGRP; j++) m = fmaxf(m, val[j]);
#pragma unroll
        for (int off = 16; off > 0; off >>= 1)
            m = fmaxf(m, __shfl_xor_sync(FULL, m, off));
        // ~2-ulp relative window (scores are positive, O(0.3..1))
        float thr = m - fabsf(m) * 2.4e-7f;
        // min global index among candidates >= thr
        int cidx = 0x7fffffff;
#pragma unroll
        for (int j = 0; j < NGRP; j++)
            if (val[j] >= thr && cidx == 0x7fffffff) cidx = j * GSIZE + l;
#pragma unroll
        for (int off = 16; off > 0; off >>= 1)
            cidx = min(cidx, __shfl_xor_sync(FULL, cidx, off));
        int jw = cidx >> 5, lw = cidx & 31;
        float cand = 0.0f;
#pragma unroll
        for (int j = 0; j < NGRP; j++) if (j == jw) cand = orig[j];
        float w = __shfl_sync(FULL, cand, lw);
        if (l == lw) {
#pragma unroll
            for (int j = 0; j < NGRP; j++) if (j == jw) val[j] = -FLT_MAX;
        }
        wsel[r] = w;
        isel[r] = cidx;
    }

    float s = 0.0f;
#pragma unroll
    for (int r = 0; r < TOPKN; r++) s = __fadd_rn(s, wsel[r]);

    if (l == 0) {
        float* ow = out + (size_t)t * TOPKN;
        float* oi = out + (size_t)TTOT * TOPKN + (size_t)t * TOPKN;
#pragma unroll
        for (int r = 0; r < TOPKN; r++) {
            ow[r] = __fmul_rn(__fdiv_rn(wsel[r], s), 2.5f);
            oi[r] = (float)isel[r];
        }
#pragma unroll
        for (int r = 0; r < TOPKN; r++)
            atomicAdd(&g_counts[b * NEXP + isel[r]], 1.0f);
    }
}

// ---------------------------------------------------------------------------
// Per-(batch, expert) sum of sigmoid(logits) over the sequence.
// ---------------------------------------------------------------------------
__global__ __launch_bounds__(256) void ssum_kernel() {
    int row0 = blockIdx.x * 32;
    int b = row0 / SEQ;
    int e = threadIdx.x;
    float s = 0.0f;
#pragma unroll 4
    for (int r = 0; r < 32; r++) {
        float xv = g_logits[(size_t)(row0 + r) * NEXP + e];
        s += xla_sigmoid(xv);
    }
    atomicAdd(&g_ssum[b * NEXP + e], s);
}

__global__ void aux_kernel(float* __restrict__ out) {
    __shared__ float red[512];
    int i = threadIdx.x;  // 512 threads
    float term = (g_counts[i] * (1.0f / 128.0f)) * (g_ssum[i] * (1.0f / 4096.0f));
    red[i] = term;
    __syncthreads();
    for (int st = 256; st > 0; st >>= 1) {
        if (i < st) red[i] += red[i + st];
        __syncthreads();
    }
    if (i == 0) out[2 * TTOT * TOPKN] = red[0] * 0.5f * 0.001f;
}

extern "C" void kernel_launch(void* const* d_in, const int* in_sizes, int n_in,
                              void* d_out, int out_size) {
    const float* x    = (const float*)d_in[0];   // [2,4096,7168] fp32
    const float* w    = (const float*)d_in[1];   // [256,7168] fp32
    const float* bias = (const float*)d_in[2];   // [256] fp32
    float* out = (float*)d_out;                  // [T*8 weights | T*8 indices | aux]

    zero_kernel<<<1, 512>>>();
    dim3 ggrid(NEXP / 128, TTOT / 128);
    gemm_kernel<<<ggrid, 256>>>(x, w);
    route_kernel<<<TTOT / 8, 256>>>(bias, out);
    ssum_kernel<<<TTOT / 32, 256>>>();
    aux_kernel<<<1, 512>>>(out);
}

// round 8
// speedup vs baseline: 1.0567x; 1.0567x over previous
#include <cuda_runtime.h>
#include <math.h>
#include <float.h>

#define KDIM 7168
#define NEXP 256
#define NGRP 8
#define GSIZE 32
#define TOPKN 8
#define TOPG 4
#define TTOT 8192
#define BSZ 2
#define SEQ 4096

// Scratch (no cudaMalloc allowed)
__device__ float g_logits[(size_t)TTOT * NEXP];   // 8 MB
__device__ float g_counts[BSZ * NEXP];
__device__ float g_ssum[BSZ * NEXP];

// ---------------------------------------------------------------------------
// Packed fp32 helpers (Blackwell f32x2). Each lane is a full IEEE rn FMA, so
// per-accumulator rounding chains are bit-identical to scalar FFMA.
// ---------------------------------------------------------------------------
__device__ __forceinline__ void ffma2(unsigned long long& d,
                                      unsigned long long a,
                                      unsigned long long b) {
    asm("fma.rn.f32x2 %0, %1, %2, %0;" : "+l"(d) : "l"(a), "l"(b));
}
__device__ __forceinline__ unsigned long long dupf(float x) {
    unsigned long long r;
    asm("mov.b64 %0, {%1, %1};" : "=l"(r) : "f"(x));
    return r;
}

// ---------------------------------------------------------------------------
// XLA-style logistic: sigmoid(x) = 0.5 + 0.5 * tanh_xla(0.5 * x).
// ---------------------------------------------------------------------------
__device__ __forceinline__ float xla_sigmoid(float x) {
    float t  = __fmul_rn(0.5f, x);
    float tc = fminf(fmaxf(t, -7.90531110763549805f), 7.90531110763549805f);
    float x2 = __fmul_rn(tc, tc);
    float p = -2.76076847742355e-16f;
    p = __fadd_rn(__fmul_rn(p, x2),  2.00018790482477e-13f);
    p = __fadd_rn(__fmul_rn(p, x2), -8.60467152213735e-11f);
    p = __fadd_rn(__fmul_rn(p, x2),  5.12229709037114e-08f);
    p = __fadd_rn(__fmul_rn(p, x2),  1.48572235717979e-05f);
    p = __fadd_rn(__fmul_rn(p, x2),  6.37261928875436e-04f);
    p = __fadd_rn(__fmul_rn(p, x2),  4.89352455891786e-03f);
    p = __fmul_rn(p, tc);
    float q = 1.19825839466702e-06f;
    q = __fadd_rn(__fmul_rn(q, x2), 1.18534705686654e-04f);
    q = __fadd_rn(__fmul_rn(q, x2), 2.26843463243900e-03f);
    q = __fadd_rn(__fmul_rn(q, x2), 4.89352518554385e-03f);
    float th = __fdiv_rn(p, q);
    th = (fabsf(t) < 0.0004f) ? t : th;
    return __fadd_rn(0.5f, __fmul_rn(0.5f, th));
}

__global__ void zero_kernel() {
    int i = threadIdx.x;
    if (i < BSZ * NEXP) { g_counts[i] = 0.0f; g_ssum[i] = 0.0f; }
}

// ---------------------------------------------------------------------------
// GEMM: logits[t][e] = sum_k x[t][k] * W[e][k]   (NT, both K-major)
// BM=128, BN=128, BK=8, 256 threads, 8x8 micro-tile per thread.
// Accumulators packed as f32x2 pairs along e; each lane keeps the strict
// ascending-k single-accumulator IEEE-FMA chain (bit-stable — do not change).
// ---------------------------------------------------------------------------
__global__ __launch_bounds__(256) void gemm_kernel(const float* __restrict__ A,
                                                   const float* __restrict__ B) {
    __shared__ float As[8][128];
    __shared__ float Bs[8][128];
    const int tid = threadIdx.x;
    const int tx = tid & 15;
    const int ty = tid >> 4;
    const int t0 = blockIdx.y * 128;
    const int e0 = blockIdx.x * 128;
    const float* Ab = A + (size_t)t0 * KDIM;
    const float* Bb = B + (size_t)e0 * KDIM;
    const int lr = tid >> 1;          // 0..127
    const int lc = (tid & 1) * 4;     // 0 or 4

    // acc2[i][jp] holds outputs (j=2*jp, 2*jp+1): jp 0..1 -> e block 0,
    // jp 2..3 -> e block +64. Zero bits == (0.0f, 0.0f).
    unsigned long long acc2[8][4];
#pragma unroll
    for (int i = 0; i < 8; i++)
#pragma unroll
        for (int jp = 0; jp < 4; jp++) acc2[i][jp] = 0ull;

    float4 av = *(const float4*)(Ab + (size_t)lr * KDIM + lc);
    float4 bv = *(const float4*)(Bb + (size_t)lr * KDIM + lc);

    for (int k0 = 0; k0 < KDIM; k0 += 8) {
        __syncthreads();
        As[lc + 0][lr] = av.x; As[lc + 1][lr] = av.y;
        As[lc + 2][lr] = av.z; As[lc + 3][lr] = av.w;
        Bs[lc + 0][lr] = bv.x; Bs[lc + 1][lr] = bv.y;
        Bs[lc + 2][lr] = bv.z; Bs[lc + 3][lr] = bv.w;
        __syncthreads();
        if (k0 + 8 < KDIM) {
            av = *(const float4*)(Ab + (size_t)lr * KDIM + k0 + 8 + lc);
            bv = *(const float4*)(Bb + (size_t)lr * KDIM + k0 + 8 + lc);
        }
#pragma unroll
        for (int kk = 0; kk < 8; kk++) {
            float4 a0 = *(const float4*)&As[kk][ty * 4];
            float4 a1 = *(const float4*)&As[kk][64 + ty * 4];
            // b pairs straight from smem: lo word = lower address = even j
            ulonglong2 b0 = *(const ulonglong2*)&Bs[kk][tx * 4];
            ulonglong2 b1 = *(const ulonglong2*)&Bs[kk][64 + tx * 4];
            unsigned long long bb[4] = {b0.x, b0.y, b1.x, b1.y};
            float a[8] = {a0.x, a0.y, a0.z, a0.w, a1.x, a1.y, a1.z, a1.w};
#pragma unroll
            for (int i = 0; i < 8; i++) {
                unsigned long long aa = dupf(a[i]);
#pragma unroll
                for (int jp = 0; jp < 4; jp++) ffma2(acc2[i][jp], aa, bb[jp]);
            }
        }
    }

#pragma unroll
    for (int hm = 0; hm < 2; hm++) {
#pragma unroll
        for (int i = 0; i < 4; i++) {
            int row = t0 + hm * 64 + ty * 4 + i;
            float* Crow = g_logits + (size_t)row * NEXP + e0;
            int mi = hm * 4 + i;
            *(ulonglong2*)&Crow[tx * 4] =
                make_ulonglong2(acc2[mi][0], acc2[mi][1]);
            *(ulonglong2*)&Crow[64 + tx * 4] =
                make_ulonglong2(acc2[mi][2], acc2[mi][3]);
        }
    }
}

// ---------------------------------------------------------------------------
// Routing: one warp per token. Lane l owns experts {32j+l : j=0..7}.
// Top-8: warp-max score, then MIN INDEX among scores within a ~2-ulp window
// of the max (index-ascending on ulp-scale ties, matching jax.lax.top_k on
// the reference's rounded scores). DO NOT change the window semantics.
// ---------------------------------------------------------------------------
__global__ __launch_bounds__(256) void route_kernel(const float* __restrict__ bias,
                                                    float* __restrict__ out) {
    const unsigned FULL = 0xffffffffu;
    int warp = (blockIdx.x * blockDim.x + threadIdx.x) >> 5;
    int l = threadIdx.x & 31;
    if (warp >= TTOT) return;
    const int t = warp;
    const int b = t / SEQ;
    const float* lgp = g_logits + (size_t)t * NEXP;

    float orig[NGRP], val[NGRP], gscore[NGRP];
#pragma unroll
    for (int j = 0; j < NGRP; j++) {
        float xv = lgp[j * GSIZE + l];
        float s = xla_sigmoid(xv);
        orig[j] = s;
        val[j] = __fadd_rn(s, bias[j * GSIZE + l]);
    }

    // group scores: sum of top-2 (biased) per group
#pragma unroll
    for (int j = 0; j < NGRP; j++) {
        float m1 = val[j], m2 = -FLT_MAX;
#pragma unroll
        for (int off = 16; off > 0; off >>= 1) {
            float o1 = __shfl_xor_sync(FULL, m1, off);
            float o2 = __shfl_xor_sync(FULL, m2, off);
            float hi = fmaxf(m1, o1);
            float lo = fminf(m1, o1);
            m2 = fmaxf(fmaxf(m2, o2), lo);
            m1 = hi;
        }
        gscore[j] = __fadd_rn(m1, m2);
    }

    // top-4 groups (strict > => lowest index on ties)
    unsigned gsel = 0;
    for (int r = 0; r < TOPG; r++) {
        float best = -FLT_MAX; int bi = 0;
#pragma unroll
        for (int j = 0; j < NGRP; j++)
            if (!((gsel >> j) & 1u) && gscore[j] > best) { best = gscore[j]; bi = j; }
        gsel |= 1u << bi;
    }
#pragma unroll
    for (int j = 0; j < NGRP; j++)
        if (!((gsel >> j) & 1u)) val[j] = -FLT_MAX;   // exclude masked groups

    // top-8 experts with ulp-window tie handling
    float wsel[TOPKN]; int isel[TOPKN];
#pragma unroll
    for (int r = 0; r < TOPKN; r++) {
        float m = -FLT_MAX;
#pragma unroll
        for (int j = 0; j < NGRP; j++) m = fmaxf(m, val[j]);
#pragma unroll
        for (int off = 16; off > 0; off >>= 1)
            m = fmaxf(m, __shfl_xor_sync(FULL, m, off));
        float thr = m - fabsf(m) * 2.4e-7f;
        int cidx = 0x7fffffff;
#pragma unroll
        for (int j = 0; j < NGRP; j++)
            if (val[j] >= thr && cidx == 0x7fffffff) cidx = j * GSIZE + l;
#pragma unroll
        for (int off = 16; off > 0; off >>= 1)
            cidx = min(cidx, __shfl_xor_sync(FULL, cidx, off));
        int jw = cidx >> 5, lw = cidx & 31;
        float cand = 0.0f;
#pragma unroll
        for (int j = 0; j < NGRP; j++) if (j == jw) cand = orig[j];
        float w = __shfl_sync(FULL, cand, lw);
        if (l == lw) {
#pragma unroll
            for (int j = 0; j < NGRP; j++) if (j == jw) val[j] = -FLT_MAX;
        }
        wsel[r] = w;
        isel[r] = cidx;
    }

    float s = 0.0f;
#pragma unroll
    for (int r = 0; r < TOPKN; r++) s = __fadd_rn(s, wsel[r]);

    if (l == 0) {
        float* ow = out + (size_t)t * TOPKN;
        float* oi = out + (size_t)TTOT * TOPKN + (size_t)t * TOPKN;
#pragma unroll
        for (int r = 0; r < TOPKN; r++) {
            ow[r] = __fmul_rn(__fdiv_rn(wsel[r], s), 2.5f);
            oi[r] = (float)isel[r];
        }
#pragma unroll
        for (int r = 0; r < TOPKN; r++)
            atomicAdd(&g_counts[b * NEXP + isel[r]], 1.0f);
    }
}

// ---------------------------------------------------------------------------
// Per-(batch, expert) sum of sigmoid(logits) over the sequence.
// 512 blocks x 16 rows for better memory-level parallelism.
// ---------------------------------------------------------------------------
__global__ __launch_bounds__(256) void ssum_kernel() {
    int row0 = blockIdx.x * 16;
    int b = row0 / SEQ;
    int e = threadIdx.x;
    float s = 0.0f;
#pragma unroll 8
    for (int r = 0; r < 16; r++) {
        float xv = g_logits[(size_t)(row0 + r) * NEXP + e];
        s += xla_sigmoid(xv);
    }
    atomicAdd(&g_ssum[b * NEXP + e], s);
}

__global__ void aux_kernel(float* __restrict__ out) {
    __shared__ float red[512];
    int i = threadIdx.x;  // 512 threads
    float term = (g_counts[i] * (1.0f / 128.0f)) * (g_ssum[i] * (1.0f / 4096.0f));
    red[i] = term;
    __syncthreads();
    for (int st = 256; st > 0; st >>= 1) {
        if (i < st) red[i] += red[i + st];
        __syncthreads();
    }
    if (i == 0) out[2 * TTOT * TOPKN] = red[0] * 0.5f * 0.001f;
}

extern "C" void kernel_launch(void* const* d_in, const int* in_sizes, int n_in,
                              void* d_out, int out_size) {
    const float* x    = (const float*)d_in[0];   // [2,4096,7168] fp32
    const float* w    = (const float*)d_in[1];   // [256,7168] fp32
    const float* bias = (const float*)d_in[2];   // [256] fp32
    float* out = (float*)d_out;                  // [T*8 weights | T*8 indices | aux]

    zero_kernel<<<1, 512>>>();
    dim3 ggrid(NEXP / 128, TTOT / 128);
    gemm_kernel<<<ggrid, 256>>>(x, w);
    route_kernel<<<TTOT / 8, 256>>>(bias, out);
    ssum_kernel<<<TTOT / 16, 256>>>();
    aux_kernel<<<1, 512>>>(out);
}